// round 9
// baseline (speedup 1.0000x reference)
#include <cuda_runtime.h>
#include <math_constants.h>

#define DIMN 128
#define NH   8
#define HD   16
#define MAXN 50000
#define MAXE 800000
#define ROWS 16   // rows per proj block

// Scratch (device globals: no allocation allowed)
__device__ float g_q[MAXN * DIMN];
__device__ float g_k[MAXN * DIMN];
__device__ float g_v[MAXN * DIMN];
__device__ float g_agg[MAXN * DIMN];
__device__ float g_m[MAXN * NH];
__device__ float g_s[MAXN * NH];
__device__ float g_p[MAXE * NH];

// ---------------------------------------------------------------------------
// init: m = -inf, s = 0, agg = 0
// ---------------------------------------------------------------------------
__global__ void init_kernel(int n)
{
    int i = blockIdx.x * blockDim.x + threadIdx.x;
    int nh = n * NH;
    if (i < nh) {
        g_m[i] = -CUDART_INF_F;
        g_s[i] = 0.0f;
    }
    int nd4 = n * DIMN / 4;
    if (i < nd4) {
        ((float4*)g_agg)[i] = make_float4(0.f, 0.f, 0.f, 0.f);
    }
}

// ---------------------------------------------------------------------------
// proj: out[r, :] = x[r, :] @ W^T + b   (W is [DIM, DIM] row-major, nn.Linear)
// Block: 128 threads, each thread owns one output column for ROWS rows.
// ---------------------------------------------------------------------------
__global__ void __launch_bounds__(DIMN) proj_kernel(
    const float* __restrict__ x, const float* __restrict__ W,
    const float* __restrict__ bias, float* __restrict__ out, int n)
{
    __shared__ float xs[ROWS * DIMN];
    const int t = threadIdx.x;
    const int base = blockIdx.x * ROWS;
    const int nrows = min(ROWS, n - base);

    for (int idx = t; idx < nrows * DIMN; idx += DIMN)
        xs[idx] = x[base * DIMN + idx];
    __syncthreads();

    float acc[ROWS];
#pragma unroll
    for (int r = 0; r < ROWS; r++) acc[r] = 0.f;

    const float4* Wv = reinterpret_cast<const float4*>(W) + t * (DIMN / 4);
    const float4* xv = reinterpret_cast<const float4*>(xs);
#pragma unroll 8
    for (int i4 = 0; i4 < DIMN / 4; i4++) {
        float4 w = __ldg(&Wv[i4]);
#pragma unroll
        for (int r = 0; r < ROWS; r++) {
            float4 xr = xv[r * (DIMN / 4) + i4];
            acc[r] += w.x * xr.x + w.y * xr.y + w.z * xr.z + w.w * xr.w;
        }
    }
    float b = __ldg(&bias[t]);
    for (int r = 0; r < nrows; r++)
        out[(base + r) * DIMN + t] = acc[r] + b;
}

// ---------------------------------------------------------------------------
// atomic float max via int/uint trick
// ---------------------------------------------------------------------------
__device__ __forceinline__ void atomicMaxFloat(float* addr, float v)
{
    if (v >= 0.0f) atomicMax((int*)addr, __float_as_int(v));
    else           atomicMin((unsigned int*)addr, __float_as_uint(v));
}

// ---------------------------------------------------------------------------
// pass A: score[e,h] = dot(q[src,h,:], k[tgt,h,:]) / 4 ; segment max into g_m
// one thread per (edge, head).  edge_index is INT32 (JAX x64 disabled).
// ---------------------------------------------------------------------------
__global__ void scores_kernel(const int* __restrict__ ei, int E)
{
    int idx = blockIdx.x * blockDim.x + threadIdx.x;
    if (idx >= E * NH) return;
    int e = idx >> 3;
    int h = idx & 7;
    int tgt = ei[e];
    int src = ei[E + e];

    const float4* qp = (const float4*)&g_q[src * DIMN + h * HD];
    const float4* kp = (const float4*)&g_k[tgt * DIMN + h * HD];
    float sum = 0.f;
#pragma unroll
    for (int i = 0; i < 4; i++) {
        float4 a = qp[i];
        float4 b = kp[i];
        sum += a.x * b.x + a.y * b.y + a.z * b.z + a.w * b.w;
    }
    sum *= 0.25f;  // 1/sqrt(HD=16)
    g_p[idx] = sum;
    atomicMaxFloat(&g_m[tgt * NH + h], sum);
}

// ---------------------------------------------------------------------------
// pass B: p = exp(score - m[tgt]); segment sum into g_s
// ---------------------------------------------------------------------------
__global__ void expsum_kernel(const int* __restrict__ ei, int E)
{
    int idx = blockIdx.x * blockDim.x + threadIdx.x;
    if (idx >= E * NH) return;
    int e = idx >> 3;
    int h = idx & 7;
    int tgt = ei[e];
    float p = __expf(g_p[idx] - g_m[tgt * NH + h]);
    g_p[idx] = p;
    atomicAdd(&g_s[tgt * NH + h], p);
}

// ---------------------------------------------------------------------------
// pass C: agg[tgt] += v[src] * (p / s[tgt])   (per head)
// 32 threads per edge, one float4 each; vector atomicAdd (RED.F32.V4)
// ---------------------------------------------------------------------------
__global__ void agg_kernel(const int* __restrict__ ei, int E)
{
    int gid = blockIdx.x * blockDim.x + threadIdx.x;
    int e = gid >> 5;
    if (e >= E) return;
    int j = gid & 31;        // float4 slot within the 128-dim row
    int h = j >> 2;          // head

    int tgt = ei[e];
    int src = ei[E + e];

    float prob = g_p[e * NH + h] / g_s[tgt * NH + h];
    float4 v = ((const float4*)&g_v[src * DIMN])[j];
    float4 contrib = make_float4(v.x * prob, v.y * prob, v.z * prob, v.w * prob);
#if __CUDA_ARCH__ >= 900
    atomicAdd(reinterpret_cast<float4*>(&g_agg[tgt * DIMN + j * 4]), contrib);
#else
    float* dst = &g_agg[tgt * DIMN + j * 4];
    atomicAdd(dst + 0, contrib.x);
    atomicAdd(dst + 1, contrib.y);
    atomicAdd(dst + 2, contrib.z);
    atomicAdd(dst + 3, contrib.w);
#endif
}

// ---------------------------------------------------------------------------
extern "C" void kernel_launch(void* const* d_in, const int* in_sizes, int n_in,
                              void* d_out, int out_size)
{
    const float* x   = (const float*)d_in[0];
    const int*   ei  = (const int*)d_in[1];
    const float* Wq  = (const float*)d_in[2];
    const float* bq  = (const float*)d_in[3];
    const float* Wk  = (const float*)d_in[4];
    const float* bk  = (const float*)d_in[5];
    const float* Wv  = (const float*)d_in[6];
    const float* bv  = (const float*)d_in[7];
    const float* Wo  = (const float*)d_in[8];
    const float* bo  = (const float*)d_in[9];
    float*       out = (float*)d_out;

    int n = in_sizes[0] / DIMN;
    int E = in_sizes[1] / 2;

    float *q, *k, *v, *agg;
    cudaGetSymbolAddress((void**)&q,   g_q);
    cudaGetSymbolAddress((void**)&k,   g_k);
    cudaGetSymbolAddress((void**)&v,   g_v);
    cudaGetSymbolAddress((void**)&agg, g_agg);

    {
        int tot = n * DIMN / 4;  // covers both agg/4 and n*NH
        if (n * NH > tot) tot = n * NH;
        init_kernel<<<(tot + 255) / 256, 256>>>(n);
    }

    int pblocks = (n + ROWS - 1) / ROWS;
    proj_kernel<<<pblocks, DIMN>>>(x, Wq, bq, q, n);
    proj_kernel<<<pblocks, DIMN>>>(x, Wk, bk, k, n);
    proj_kernel<<<pblocks, DIMN>>>(x, Wv, bv, v, n);

    int eh = E * NH;
    scores_kernel<<<(eh + 255) / 256, 256>>>(ei, E);
    expsum_kernel<<<(eh + 255) / 256, 256>>>(ei, E);

    long long e32 = (long long)E * 32;
    agg_kernel<<<(int)((e32 + 255) / 256), 256>>>(ei, E);

    proj_kernel<<<pblocks, DIMN>>>(agg, Wo, bo, out, n);
}

// round 10
// speedup vs baseline: 1.4975x; 1.4975x over previous
#include <cuda_runtime.h>

#define DIMN 128
#define NH   8
#define MAXN 50000
#define MAXE 800000
#define SROW 132                 // smem row stride in floats (padded)
#define PROJ_SMEM (2 * 128 * SROW * 4)

// Scratch (device globals: no allocation allowed)
__device__ float g_q[MAXN * DIMN];
__device__ float g_k[MAXN * DIMN];
__device__ float g_v[MAXN * DIMN];
__device__ float g_agg[MAXN * DIMN];
__device__ float g_s[MAXN * NH];
__device__ float g_p[MAXE * NH];

// ---------------------------------------------------------------------------
// packed f32x2 helpers (sm_100+)
// ---------------------------------------------------------------------------
__device__ __forceinline__ unsigned long long pack2(float x, float y)
{
    unsigned long long r;
    asm("mov.b64 %0, {%1, %2};" : "=l"(r) : "f"(x), "f"(y));
    return r;
}
__device__ __forceinline__ void unpack2(unsigned long long v, float& x, float& y)
{
    asm("mov.b64 {%0, %1}, %2;" : "=f"(x), "=f"(y) : "l"(v));
}
__device__ __forceinline__ unsigned long long fma2(unsigned long long a,
                                                   unsigned long long b,
                                                   unsigned long long c)
{
    unsigned long long d;
    asm("fma.rn.f32x2 %0, %1, %2, %3;" : "=l"(d) : "l"(a), "l"(b), "l"(c));
    return d;
}

// smem word offset for element [k][c] of a transposed 128x128 tile,
// XOR-swizzled at float4 granularity to spread banks on the transpose store.
__device__ __forceinline__ int sw_off(int k, int c4, int c3)
{
    int f = ((k >> 2) + (k >> 5)) & 7;
    return k * SROW + ((c4 ^ f) << 2) + c3;
}

// ---------------------------------------------------------------------------
// init: s = 0, agg = 0
// ---------------------------------------------------------------------------
__global__ void init_kernel(int n)
{
    int i = blockIdx.x * blockDim.x + threadIdx.x;
    if (i < n * (DIMN / 4))
        ((float4*)g_agg)[i] = make_float4(0.f, 0.f, 0.f, 0.f);
    if (i < n * NH)
        g_s[i] = 0.0f;
}

// ---------------------------------------------------------------------------
// Tiled SGEMM body: out[r,c] = sum_k x[r,k] * W[c,k] + b[c]   (x @ W^T + b)
// Block: 256 threads (16x16), tile 128 rows x 128 cols, 8x8 microtile,
// f32x2-packed accumulation (pairs of adjacent rows).
// ---------------------------------------------------------------------------
__device__ __forceinline__ void proj_body(
    const float* __restrict__ x, const float* __restrict__ W,
    const float* __restrict__ bias, float* __restrict__ out, int n,
    float* ws, float* xs)
{
    const int tid  = threadIdx.x;
    const int base = blockIdx.x * 128;

    // Stage W^T and x^T tiles into swizzled smem: ws[k][c] = W[c][k],
    // xs[k][r] = x[base+r][k]
    {
        const int lane = tid & 31;      // covers k in float4 chunks
        const int cw   = tid >> 5;      // 8 rows/cols per pass
        const int k0   = lane * 4;
        for (int c = cw; c < 128; c += 8) {
            float4 w = __ldg((const float4*)(W + c * 128) + lane);
            int c4 = c >> 2, c3 = c & 3;
            ws[sw_off(k0 + 0, c4, c3)] = w.x;
            ws[sw_off(k0 + 1, c4, c3)] = w.y;
            ws[sw_off(k0 + 2, c4, c3)] = w.z;
            ws[sw_off(k0 + 3, c4, c3)] = w.w;

            int gr = base + c;
            float4 xv = (gr < n) ? __ldg((const float4*)(x + (size_t)gr * 128) + lane)
                                 : make_float4(0.f, 0.f, 0.f, 0.f);
            xs[sw_off(k0 + 0, c4, c3)] = xv.x;
            xs[sw_off(k0 + 1, c4, c3)] = xv.y;
            xs[sw_off(k0 + 2, c4, c3)] = xv.z;
            xs[sw_off(k0 + 3, c4, c3)] = xv.w;
        }
    }
    __syncthreads();

    const int tx = tid & 15;   // col group: cols tx*8 .. +8
    const int ty = tid >> 4;   // row group: rows ty*8 .. +8

    unsigned long long acc[4][8];   // [row-pair][col], packed {even row, odd row}
#pragma unroll
    for (int i = 0; i < 4; i++)
#pragma unroll
        for (int j = 0; j < 8; j++) acc[i][j] = 0ULL;

#pragma unroll 16
    for (int k = 0; k < 128; k++) {
        int f  = ((k >> 2) + (k >> 5)) & 7;
        int ro = k * SROW;
        // a-frag: 8 row values = 4 packed pairs (bit-exact reinterpret)
        ulonglong2 a01 = *(const ulonglong2*)(xs + ro + ((((ty * 2 + 0) ^ f)) << 2));
        ulonglong2 a23 = *(const ulonglong2*)(xs + ro + ((((ty * 2 + 1) ^ f)) << 2));
        // b-frag: 8 col weights, broadcast-packed
        float4 w0 = *(const float4*)(ws + ro + ((((tx * 2 + 0) ^ f)) << 2));
        float4 w1 = *(const float4*)(ws + ro + ((((tx * 2 + 1) ^ f)) << 2));
        unsigned long long aa[4] = { a01.x, a01.y, a23.x, a23.y };
        unsigned long long bb[8];
        bb[0] = pack2(w0.x, w0.x); bb[1] = pack2(w0.y, w0.y);
        bb[2] = pack2(w0.z, w0.z); bb[3] = pack2(w0.w, w0.w);
        bb[4] = pack2(w1.x, w1.x); bb[5] = pack2(w1.y, w1.y);
        bb[6] = pack2(w1.z, w1.z); bb[7] = pack2(w1.w, w1.w);
#pragma unroll
        for (int i = 0; i < 4; i++)
#pragma unroll
            for (int j = 0; j < 8; j++)
                acc[i][j] = fma2(aa[i], bb[j], acc[i][j]);
    }

    // epilogue: unpack, add bias, store
    float4 b0 = __ldg((const float4*)bias + tx * 2);
    float4 b1 = __ldg((const float4*)bias + tx * 2 + 1);
#pragma unroll
    for (int i = 0; i < 4; i++) {
        int r0 = base + ty * 8 + i * 2;
        float lo[8], hi[8];
#pragma unroll
        for (int j = 0; j < 8; j++) unpack2(acc[i][j], lo[j], hi[j]);
        if (r0 < n) {
            float4 o0 = make_float4(lo[0] + b0.x, lo[1] + b0.y, lo[2] + b0.z, lo[3] + b0.w);
            float4 o1 = make_float4(lo[4] + b1.x, lo[5] + b1.y, lo[6] + b1.z, lo[7] + b1.w);
            float4* op = (float4*)(out + (size_t)r0 * 128);
            op[tx * 2] = o0; op[tx * 2 + 1] = o1;
        }
        if (r0 + 1 < n) {
            float4 o0 = make_float4(hi[0] + b0.x, hi[1] + b0.y, hi[2] + b0.z, hi[3] + b0.w);
            float4 o1 = make_float4(hi[4] + b1.x, hi[5] + b1.y, hi[6] + b1.z, hi[7] + b1.w);
            float4* op = (float4*)(out + (size_t)(r0 + 1) * 128);
            op[tx * 2] = o0; op[tx * 2 + 1] = o1;
        }
    }
}

// fused q/k/v projection: blockIdx.y selects the weight set
__global__ void __launch_bounds__(256, 1) proj3_kernel(
    const float* __restrict__ x,
    const float* __restrict__ Wq, const float* __restrict__ bq,
    const float* __restrict__ Wk, const float* __restrict__ bk,
    const float* __restrict__ Wv, const float* __restrict__ bv, int n)
{
    extern __shared__ float sm[];
    const float *W, *b; float* o;
    if (blockIdx.y == 0)      { W = Wq; b = bq; o = g_q; }
    else if (blockIdx.y == 1) { W = Wk; b = bk; o = g_k; }
    else                      { W = Wv; b = bv; o = g_v; }
    proj_body(x, W, b, o, n, sm, sm + 128 * SROW);
}

__global__ void __launch_bounds__(256, 1) projo_kernel(
    const float* __restrict__ W, const float* __restrict__ b,
    float* __restrict__ out, int n)
{
    extern __shared__ float sm[];
    proj_body(g_agg, W, b, out, n, sm, sm + 128 * SROW);
}

// ---------------------------------------------------------------------------
// scores + exp + segment-sum (no max subtraction: softmax shift-invariant,
// scores are O(+-8) so exp is fp32-safe). Warp per edge, quad per head.
// ---------------------------------------------------------------------------
__global__ void scores_kernel(const int* __restrict__ ei, int E)
{
    int gid = blockIdx.x * blockDim.x + threadIdx.x;
    int e = gid >> 5;
    if (e >= E) return;
    int lane = gid & 31;
    int tgt = __ldg(&ei[e]);
    int src = __ldg(&ei[E + e]);

    float4 qv = ((const float4*)&g_q[(size_t)src * DIMN])[lane];
    float4 kv = ((const float4*)&g_k[(size_t)tgt * DIMN])[lane];
    float s4 = qv.x * kv.x + qv.y * kv.y + qv.z * kv.z + qv.w * kv.w;
    s4 += __shfl_xor_sync(0xFFFFFFFFu, s4, 1);
    s4 += __shfl_xor_sync(0xFFFFFFFFu, s4, 2);   // quad = one head's dot

    if ((lane & 3) == 0) {
        int h = lane >> 2;
        float p = __expf(s4 * 0.25f);   // 1/sqrt(16)
        g_p[e * NH + h] = p;
        atomicAdd(&g_s[tgt * NH + h], p);
    }
}

// s -> 1/s (empty segments stay 0, never read)
__global__ void rcp_kernel(int n)
{
    int i = blockIdx.x * blockDim.x + threadIdx.x;
    if (i < n * NH) {
        float s = g_s[i];
        g_s[i] = (s > 0.f) ? __frcp_rn(s) : 0.f;
    }
}

// ---------------------------------------------------------------------------
// agg[tgt] += v[src] * p * (1/s[tgt]) — warp per edge, float4 vector RED
// ---------------------------------------------------------------------------
__global__ void agg_kernel(const int* __restrict__ ei, int E)
{
    int gid = blockIdx.x * blockDim.x + threadIdx.x;
    int e = gid >> 5;
    if (e >= E) return;
    int lane = gid & 31;
    int h = lane >> 2;

    int tgt = __ldg(&ei[e]);
    int src = __ldg(&ei[E + e]);

    float prob = g_p[e * NH + h] * g_s[tgt * NH + h];
    float4 v = ((const float4*)&g_v[(size_t)src * DIMN])[lane];
    float4 contrib = make_float4(v.x * prob, v.y * prob, v.z * prob, v.w * prob);
    atomicAdd((float4*)&g_agg[(size_t)tgt * DIMN + lane * 4], contrib);
}

// ---------------------------------------------------------------------------
extern "C" void kernel_launch(void* const* d_in, const int* in_sizes, int n_in,
                              void* d_out, int out_size)
{
    const float* x   = (const float*)d_in[0];
    const int*   ei  = (const int*)d_in[1];
    const float* Wq  = (const float*)d_in[2];
    const float* bq  = (const float*)d_in[3];
    const float* Wk  = (const float*)d_in[4];
    const float* bk  = (const float*)d_in[5];
    const float* Wv  = (const float*)d_in[6];
    const float* bv  = (const float*)d_in[7];
    const float* Wo  = (const float*)d_in[8];
    const float* bo  = (const float*)d_in[9];
    float*       out = (float*)d_out;

    int n = in_sizes[0] / DIMN;
    int E = in_sizes[1] / 2;

    cudaFuncSetAttribute(proj3_kernel, cudaFuncAttributeMaxDynamicSharedMemorySize, PROJ_SMEM);
    cudaFuncSetAttribute(projo_kernel, cudaFuncAttributeMaxDynamicSharedMemorySize, PROJ_SMEM);

    init_kernel<<<(n * (DIMN / 4) + 255) / 256, 256>>>(n);

    int pblocks = (n + 127) / 128;
    proj3_kernel<<<dim3(pblocks, 3), 256, PROJ_SMEM>>>(x, Wq, bq, Wk, bk, Wv, bv, n);

    long long et = (long long)E * 32;
    scores_kernel<<<(int)((et + 255) / 256), 256>>>(ei, E);
    rcp_kernel<<<(n * NH + 255) / 256, 256>>>(n);
    agg_kernel<<<(int)((et + 255) / 256), 256>>>(ei, E);

    projo_kernel<<<pblocks, 256, PROJ_SMEM>>>(Wo, bo, out, n);
}

// round 11
// speedup vs baseline: 1.7310x; 1.1559x over previous
#include <cuda_runtime.h>

#define DIMN 128
#define NH   8
#define MAXN 50000
#define MAXE 800000
#define SROW 132                 // smem row stride in floats (padded)
#define PROJ_SMEM (2 * 128 * SROW * 4)

// Scratch (device globals: no allocation allowed)
__device__ float g_q[MAXN * DIMN];
__device__ float g_k[MAXN * DIMN];
__device__ float g_v[MAXN * DIMN];
__device__ float g_agg[MAXN * DIMN];   // UNNORMALIZED sum p*v
__device__ float g_s[MAXN * NH];       // sum p, then 1/sum p after rcp_kernel

// ---------------------------------------------------------------------------
// packed f32x2 helpers (sm_100+)
// ---------------------------------------------------------------------------
__device__ __forceinline__ unsigned long long pack2(float x, float y)
{
    unsigned long long r;
    asm("mov.b64 %0, {%1, %2};" : "=l"(r) : "f"(x), "f"(y));
    return r;
}
__device__ __forceinline__ void unpack2(unsigned long long v, float& x, float& y)
{
    asm("mov.b64 {%0, %1}, %2;" : "=f"(x), "=f"(y) : "l"(v));
}
__device__ __forceinline__ unsigned long long fma2(unsigned long long a,
                                                   unsigned long long b,
                                                   unsigned long long c)
{
    unsigned long long d;
    asm("fma.rn.f32x2 %0, %1, %2, %3;" : "=l"(d) : "l"(a), "l"(b), "l"(c));
    return d;
}

// smem word offset for element [k][c] of a transposed 128x128 tile,
// XOR-swizzled at float4 granularity to spread banks on the transpose store.
__device__ __forceinline__ int sw_off(int k, int c4, int c3)
{
    int f = ((k >> 2) + (k >> 5)) & 7;
    return k * SROW + ((c4 ^ f) << 2) + c3;
}

// ---------------------------------------------------------------------------
// init: s = 0, agg = 0
// ---------------------------------------------------------------------------
__global__ void init_kernel(int n)
{
    int i = blockIdx.x * blockDim.x + threadIdx.x;
    if (i < n * (DIMN / 4))
        ((float4*)g_agg)[i] = make_float4(0.f, 0.f, 0.f, 0.f);
    if (i < n * NH)
        g_s[i] = 0.0f;
}

// ---------------------------------------------------------------------------
// Tiled SGEMM body: out[r,c] = sum_k xin[r,k]*scale(r,k) * W[c,k] + b[c]
// scale==nullptr -> 1.  scale indexed [r*NH + k/16] (per-head normalizer).
// Block: 256 threads (16x16), tile 128x128, 8x8 microtile, f32x2 accum.
// ---------------------------------------------------------------------------
__device__ __forceinline__ void proj_body(
    const float* __restrict__ x, const float* __restrict__ W,
    const float* __restrict__ bias, float* __restrict__ out, int n,
    const float* __restrict__ scale,
    float* ws, float* xs)
{
    const int tid  = threadIdx.x;
    const int base = blockIdx.x * 128;

    // Stage W^T and x^T tiles into swizzled smem: ws[k][c] = W[c][k],
    // xs[k][r] = x[base+r][k] * (scale ? scale[base+r][k/16] : 1)
    {
        const int lane = tid & 31;      // covers k in float4 chunks
        const int cw   = tid >> 5;      // 8 rows/cols per pass
        const int k0   = lane * 4;
        for (int c = cw; c < 128; c += 8) {
            float4 w = __ldg((const float4*)(W + c * 128) + lane);
            int c4 = c >> 2, c3 = c & 3;
            ws[sw_off(k0 + 0, c4, c3)] = w.x;
            ws[sw_off(k0 + 1, c4, c3)] = w.y;
            ws[sw_off(k0 + 2, c4, c3)] = w.z;
            ws[sw_off(k0 + 3, c4, c3)] = w.w;

            int gr = base + c;
            float4 xv = make_float4(0.f, 0.f, 0.f, 0.f);
            if (gr < n) {
                xv = __ldg((const float4*)(x + (size_t)gr * 128) + lane);
                if (scale) {
                    float sc = __ldg(&scale[gr * NH + (lane >> 2)]);
                    xv.x *= sc; xv.y *= sc; xv.z *= sc; xv.w *= sc;
                }
            }
            xs[sw_off(k0 + 0, c4, c3)] = xv.x;
            xs[sw_off(k0 + 1, c4, c3)] = xv.y;
            xs[sw_off(k0 + 2, c4, c3)] = xv.z;
            xs[sw_off(k0 + 3, c4, c3)] = xv.w;
        }
    }
    __syncthreads();

    const int tx = tid & 15;   // col group: cols tx*8 .. +8
    const int ty = tid >> 4;   // row group: rows ty*8 .. +8

    unsigned long long acc[4][8];   // [row-pair][col], packed {even row, odd row}
#pragma unroll
    for (int i = 0; i < 4; i++)
#pragma unroll
        for (int j = 0; j < 8; j++) acc[i][j] = 0ULL;

#pragma unroll 16
    for (int k = 0; k < 128; k++) {
        int f  = ((k >> 2) + (k >> 5)) & 7;
        int ro = k * SROW;
        ulonglong2 a01 = *(const ulonglong2*)(xs + ro + ((((ty * 2 + 0) ^ f)) << 2));
        ulonglong2 a23 = *(const ulonglong2*)(xs + ro + ((((ty * 2 + 1) ^ f)) << 2));
        float4 w0 = *(const float4*)(ws + ro + ((((tx * 2 + 0) ^ f)) << 2));
        float4 w1 = *(const float4*)(ws + ro + ((((tx * 2 + 1) ^ f)) << 2));
        unsigned long long aa[4] = { a01.x, a01.y, a23.x, a23.y };
        unsigned long long bb[8];
        bb[0] = pack2(w0.x, w0.x); bb[1] = pack2(w0.y, w0.y);
        bb[2] = pack2(w0.z, w0.z); bb[3] = pack2(w0.w, w0.w);
        bb[4] = pack2(w1.x, w1.x); bb[5] = pack2(w1.y, w1.y);
        bb[6] = pack2(w1.z, w1.z); bb[7] = pack2(w1.w, w1.w);
#pragma unroll
        for (int i = 0; i < 4; i++)
#pragma unroll
            for (int j = 0; j < 8; j++)
                acc[i][j] = fma2(aa[i], bb[j], acc[i][j]);
    }

    // epilogue: unpack, add bias, store
    float4 b0 = __ldg((const float4*)bias + tx * 2);
    float4 b1 = __ldg((const float4*)bias + tx * 2 + 1);
#pragma unroll
    for (int i = 0; i < 4; i++) {
        int r0 = base + ty * 8 + i * 2;
        float lo[8], hi[8];
#pragma unroll
        for (int j = 0; j < 8; j++) unpack2(acc[i][j], lo[j], hi[j]);
        if (r0 < n) {
            float4 o0 = make_float4(lo[0] + b0.x, lo[1] + b0.y, lo[2] + b0.z, lo[3] + b0.w);
            float4 o1 = make_float4(lo[4] + b1.x, lo[5] + b1.y, lo[6] + b1.z, lo[7] + b1.w);
            float4* op = (float4*)(out + (size_t)r0 * 128);
            op[tx * 2] = o0; op[tx * 2 + 1] = o1;
        }
        if (r0 + 1 < n) {
            float4 o0 = make_float4(hi[0] + b0.x, hi[1] + b0.y, hi[2] + b0.z, hi[3] + b0.w);
            float4 o1 = make_float4(hi[4] + b1.x, hi[5] + b1.y, hi[6] + b1.z, hi[7] + b1.w);
            float4* op = (float4*)(out + (size_t)(r0 + 1) * 128);
            op[tx * 2] = o0; op[tx * 2 + 1] = o1;
        }
    }
}

// fused q/k/v projection: blockIdx.y selects the weight set
__global__ void __launch_bounds__(256, 1) proj3_kernel(
    const float* __restrict__ x,
    const float* __restrict__ Wq, const float* __restrict__ bq,
    const float* __restrict__ Wk, const float* __restrict__ bk,
    const float* __restrict__ Wv, const float* __restrict__ bv, int n)
{
    extern __shared__ float sm[];
    const float *W, *b; float* o;
    if (blockIdx.y == 0)      { W = Wq; b = bq; o = g_q; }
    else if (blockIdx.y == 1) { W = Wk; b = bk; o = g_k; }
    else                      { W = Wv; b = bv; o = g_v; }
    proj_body(x, W, b, o, n, nullptr, sm, sm + 128 * SROW);
}

// output projection with fused per-head softmax normalization of agg input
__global__ void __launch_bounds__(256, 1) projo_kernel(
    const float* __restrict__ W, const float* __restrict__ b,
    float* __restrict__ out, int n)
{
    extern __shared__ float sm[];
    proj_body(g_agg, W, b, out, n, g_s, sm, sm + 128 * SROW);
}

// ---------------------------------------------------------------------------
// FUSED edge pass: per edge, per head h:
//   p = exp(q[src,h]·k[tgt,h] / 4)        (softmax shift-invariance, no max)
//   g_s[tgt,h]   += p                      (scalar RED)
//   g_agg[tgt,:] += p * v[src,:]           (float4 vector RED)
// Warp per edge; lane owns float4 j of the 128-dim row; quad = one head.
// ---------------------------------------------------------------------------
__global__ void edge_kernel(const int* __restrict__ ei, int E)
{
    int gid = blockIdx.x * blockDim.x + threadIdx.x;
    int e = gid >> 5;
    if (e >= E) return;
    int lane = gid & 31;
    int tgt = __ldg(&ei[e]);
    int src = __ldg(&ei[E + e]);

    float4 qv = __ldg(((const float4*)&g_q[(size_t)src * DIMN]) + lane);
    float4 kv = __ldg(((const float4*)&g_k[(size_t)tgt * DIMN]) + lane);
    float s4 = qv.x * kv.x + qv.y * kv.y + qv.z * kv.z + qv.w * kv.w;
    s4 += __shfl_xor_sync(0xFFFFFFFFu, s4, 1);
    s4 += __shfl_xor_sync(0xFFFFFFFFu, s4, 2);   // all 4 lanes of quad hold head dot

    float p = __expf(s4 * 0.25f);                // 1/sqrt(HD=16)

    if ((lane & 3) == 0)
        atomicAdd(&g_s[tgt * NH + (lane >> 2)], p);

    float4 vv = __ldg(((const float4*)&g_v[(size_t)src * DIMN]) + lane);
    float4 contrib = make_float4(vv.x * p, vv.y * p, vv.z * p, vv.w * p);
    atomicAdd((float4*)&g_agg[(size_t)tgt * DIMN + lane * 4], contrib);
}

// s -> 1/s (empty segments stay 0; their agg rows are 0 anyway)
__global__ void rcp_kernel(int n)
{
    int i = blockIdx.x * blockDim.x + threadIdx.x;
    if (i < n * NH) {
        float s = g_s[i];
        g_s[i] = (s > 0.f) ? __frcp_rn(s) : 0.f;
    }
}

// ---------------------------------------------------------------------------
extern "C" void kernel_launch(void* const* d_in, const int* in_sizes, int n_in,
                              void* d_out, int out_size)
{
    const float* x   = (const float*)d_in[0];
    const int*   ei  = (const int*)d_in[1];
    const float* Wq  = (const float*)d_in[2];
    const float* bq  = (const float*)d_in[3];
    const float* Wk  = (const float*)d_in[4];
    const float* bk  = (const float*)d_in[5];
    const float* Wv  = (const float*)d_in[6];
    const float* bv  = (const float*)d_in[7];
    const float* Wo  = (const float*)d_in[8];
    const float* bo  = (const float*)d_in[9];
    float*       out = (float*)d_out;

    int n = in_sizes[0] / DIMN;
    int E = in_sizes[1] / 2;

    cudaFuncSetAttribute(proj3_kernel, cudaFuncAttributeMaxDynamicSharedMemorySize, PROJ_SMEM);
    cudaFuncSetAttribute(projo_kernel, cudaFuncAttributeMaxDynamicSharedMemorySize, PROJ_SMEM);

    init_kernel<<<(n * (DIMN / 4) + 255) / 256, 256>>>(n);

    int pblocks = (n + 127) / 128;
    proj3_kernel<<<dim3(pblocks, 3), 256, PROJ_SMEM>>>(x, Wq, bq, Wk, bk, Wv, bv, n);

    long long et = (long long)E * 32;
    edge_kernel<<<(int)((et + 255) / 256), 256>>>(ei, E);
    rcp_kernel<<<(n * NH + 255) / 256, 256>>>(n);

    projo_kernel<<<pblocks, 256, PROJ_SMEM>>>(Wo, bo, out, n);
}